// round 17
// baseline (speedup 1.0000x reference)
#include <cuda_runtime.h>

#define HW 512
#define PLANE (512*512)
#define TPB 128
#define WPB 4   // warps per block; warp = 4 tiles (32 columns)

// 0.5*cos(m*pi/16) constants and 1/sqrt(8)
#define DA  0.35355339059327373f
#define DB1 0.46193976625564337f
#define DB3 0.19134171618254492f
#define DC1 0.49039264020161522f
#define DC3 0.41573480615127262f
#define DC5 0.27778511650980114f
#define DC7 0.09754516100806417f

typedef unsigned long long u64;

// ---- packed f32x2 helpers (Blackwell SIMD fp32, PTX-only) ----
__device__ __forceinline__ u64 PK(float a, float b) {
    u64 r; asm("mov.b64 %0,{%1,%2};" : "=l"(r) : "f"(a), "f"(b)); return r;
}
__device__ __forceinline__ void UPK(u64 v, float& a, float& b) {
    asm("mov.b64 {%0,%1},%2;" : "=f"(a), "=f"(b) : "l"(v));
}
__device__ __forceinline__ u64 fadd2(u64 a, u64 b) {
    u64 r; asm("add.rn.f32x2 %0,%1,%2;" : "=l"(r) : "l"(a), "l"(b)); return r;
}
__device__ __forceinline__ u64 fmul2(u64 a, u64 b) {
    u64 r; asm("mul.rn.f32x2 %0,%1,%2;" : "=l"(r) : "l"(a), "l"(b)); return r;
}
__device__ __forceinline__ u64 ffma2(u64 a, u64 b, u64 c) {
    u64 r; asm("fma.rn.f32x2 %0,%1,%2,%3;" : "=l"(r) : "l"(a), "l"(b), "l"(c)); return r;
}
__device__ __forceinline__ u64 fsub2(u64 a, u64 b) {
    return ffma2(b, PK(-1.0f, -1.0f), a);
}

// ---- scalar DCT ----
__device__ __forceinline__ void mulD(float v[8]) {
    float s0 = v[0] + v[7], s1 = v[1] + v[6], s2 = v[2] + v[5], s3 = v[3] + v[4];
    float d0 = v[0] - v[7], d1 = v[1] - v[6], d2 = v[2] - v[5], d3 = v[3] - v[4];
    float t0 = s0 + s3, t1 = s1 + s2, t2 = s0 - s3, t3 = s1 - s2;
    v[0] = DA * (t0 + t1);
    v[4] = DA * (t0 - t1);
    v[2] = fmaf(DB1, t2,  DB3 * t3);
    v[6] = fmaf(DB3, t2, -DB1 * t3);
    v[1] = fmaf(DC1, d0, fmaf( DC3, d1, fmaf( DC5, d2,  DC7 * d3)));
    v[3] = fmaf(DC3, d0, fmaf(-DC7, d1, fmaf(-DC1, d2, -DC5 * d3)));
    v[5] = fmaf(DC5, d0, fmaf(-DC1, d1, fmaf( DC7, d2,  DC3 * d3)));
    v[7] = fmaf(DC7, d0, fmaf(-DC5, d1, fmaf( DC3, d2, -DC1 * d3)));
}

__device__ __forceinline__ void mulDT(float v[8]) {
    float ee0 = DA * (v[0] + v[4]);
    float ee1 = DA * (v[0] - v[4]);
    float eb0 = fmaf(DB1, v[2],  DB3 * v[6]);
    float eb1 = fmaf(DB3, v[2], -DB1 * v[6]);
    float E0 = ee0 + eb0, E3 = ee0 - eb0;
    float E1 = ee1 + eb1, E2 = ee1 - eb1;
    float O0 = fmaf(DC1, v[1], fmaf( DC3, v[3], fmaf( DC5, v[5],  DC7 * v[7])));
    float O1 = fmaf(DC3, v[1], fmaf(-DC7, v[3], fmaf(-DC1, v[5], -DC5 * v[7])));
    float O2 = fmaf(DC5, v[1], fmaf(-DC1, v[3], fmaf( DC7, v[5],  DC3 * v[7])));
    float O3 = fmaf(DC7, v[1], fmaf(-DC5, v[3], fmaf( DC3, v[5], -DC1 * v[7])));
    v[0] = E0 + O0; v[7] = E0 - O0;
    v[1] = E1 + O1; v[6] = E1 - O1;
    v[2] = E2 + O2; v[5] = E2 - O2;
    v[3] = E3 + O3; v[4] = E3 - O3;
}

// ---- packed f32x2 DCT (Cb,Cr) ----
__device__ __forceinline__ void mulD2(u64 v[8]) {
    const u64 CA  = PK(DA,  DA),  CB1 = PK(DB1, DB1), CB3 = PK(DB3, DB3);
    const u64 C1  = PK(DC1, DC1), C3  = PK(DC3, DC3);
    const u64 C5  = PK(DC5, DC5), C7  = PK(DC7, DC7);
    u64 s0 = fadd2(v[0], v[7]), s1 = fadd2(v[1], v[6]);
    u64 s2 = fadd2(v[2], v[5]), s3 = fadd2(v[3], v[4]);
    u64 d0 = fsub2(v[0], v[7]), d1 = fsub2(v[1], v[6]);
    u64 d2 = fsub2(v[2], v[5]), d3 = fsub2(v[3], v[4]);
    u64 t0 = fadd2(s0, s3), t1 = fadd2(s1, s2);
    u64 t2 = fsub2(s0, s3), t3 = fsub2(s1, s2);
    v[0] = fmul2(fadd2(t0, t1), CA);
    v[4] = fmul2(fsub2(t0, t1), CA);
    v[2] = ffma2(t2, CB1, fmul2(t3, CB3));
    v[6] = fsub2(fmul2(t2, CB3), fmul2(t3, CB1));
    v[1] = ffma2(d0, C1, ffma2(d1, C3, ffma2(d2, C5, fmul2(d3, C7))));
    v[3] = fsub2(fmul2(d0, C3), ffma2(d1, C7, ffma2(d2, C1, fmul2(d3, C5))));
    v[5] = fsub2(ffma2(d0, C5, ffma2(d2, C7, fmul2(d3, C3))), fmul2(d1, C1));
    v[7] = fsub2(ffma2(d0, C7, fmul2(d2, C3)), ffma2(d1, C5, fmul2(d3, C1)));
}

__device__ __forceinline__ void mulDT2(u64 v[8]) {
    const u64 CA  = PK(DA,  DA),  CB1 = PK(DB1, DB1), CB3 = PK(DB3, DB3);
    const u64 C1  = PK(DC1, DC1), C3  = PK(DC3, DC3);
    const u64 C5  = PK(DC5, DC5), C7  = PK(DC7, DC7);
    u64 ee0 = fmul2(fadd2(v[0], v[4]), CA);
    u64 ee1 = fmul2(fsub2(v[0], v[4]), CA);
    u64 eb0 = ffma2(v[2], CB1, fmul2(v[6], CB3));
    u64 eb1 = fsub2(fmul2(v[2], CB3), fmul2(v[6], CB1));
    u64 E0 = fadd2(ee0, eb0), E3 = fsub2(ee0, eb0);
    u64 E1 = fadd2(ee1, eb1), E2 = fsub2(ee1, eb1);
    u64 O0 = ffma2(v[1], C1, ffma2(v[3], C3, ffma2(v[5], C5, fmul2(v[7], C7))));
    u64 O1 = fsub2(fmul2(v[1], C3), ffma2(v[3], C7, ffma2(v[5], C1, fmul2(v[7], C5))));
    u64 O2 = fsub2(ffma2(v[1], C5, ffma2(v[5], C7, fmul2(v[7], C3))), fmul2(v[3], C1));
    u64 O3 = fsub2(ffma2(v[1], C7, fmul2(v[5], C3)), ffma2(v[3], C5, fmul2(v[7], C1)));
    v[0] = fadd2(E0, O0); v[7] = fsub2(E0, O0);
    v[1] = fadd2(E1, O1); v[6] = fsub2(E1, O1);
    v[2] = fadd2(E2, O2); v[5] = fsub2(E2, O2);
    v[3] = fadd2(E3, O3); v[4] = fsub2(E3, O3);
}

__device__ __forceinline__ float tanh_ap(float z) {
    float r; asm("tanh.approx.f32 %0,%1;" : "=f"(r) : "f"(z)); return r;
}

// packed soft-round on (a,b) with per-half tables.
// u = x - 0.5 via fma; n = rne(u) via magic three-add (per half);
// tanh(25*(u-n)) == tanh(25*(t-0.5)); result = (n + 0.5 + 0.5h)*qv.
// Valid: |x| <= 4.5 (|coef|<=8, qt>=2) so reference clamp [-10,9] never binds;
// rne integer-tie outcome-equivalent through the saturated sigmoid.
// NOTE: MAGIC-0.5 is NOT fp32-representable — the -0.5 must be a separate op (R6 bug).
#define MAGIC 12582912.0f
__device__ __forceinline__ u64 quant2p(u64 v, u64 qi2, u64 qv2) {
    const u64 NH = PK(-0.5f, -0.5f);
    const u64 MP = PK(MAGIC, MAGIC);
    const u64 MN = PK(-MAGIC, -MAGIC);
    const u64 T25 = PK(25.0f, 25.0f);
    const u64 H2 = PK(0.5f, 0.5f);
    u64 u2 = ffma2(v, qi2, NH);                    // x - 0.5
    u64 n2 = fadd2(fadd2(u2, MP), MN);             // rne(x - 0.5) = floor(x)
    u64 z2 = fmul2(fsub2(u2, n2), T25);            // 25*(t - 0.5)
    float za, zb; UPK(z2, za, zb);
    u64 h2 = PK(tanh_ap(za), tanh_ap(zb));
    u64 s2 = ffma2(h2, H2, fadd2(n2, H2));         // n + 0.5 + 0.5h
    return fmul2(s2, qv2);
}

// Per-warp union scratch: 864 floats = 3456 B.
//  - stage phase:     [ch][row][36] floats, ch<3, row<8  (3*288 = 864)
//  - transpose phase: Y tiles at floats [0,288), C tiles (u64) at floats [288,864)
#define WARP_SCRATCH 864

__global__ void __launch_bounds__(TPB, 10)
jpeg_kernel(const float* __restrict__ img, const float* __restrict__ q_y,
            const float* __restrict__ q_c, float* __restrict__ out) {
    __shared__ __align__(16) float scr[WPB][WARP_SCRATCH];
    // luma tables: stride-10 float (8B-aligned pairs for LDS.64)
    __shared__ __align__(16) float tqvy[80], tqiy[80];
    // chroma tables: pre-broadcast u64 PK(a,a), stride-10
    __shared__ __align__(16) u64 tqvc2[80], tqic2[80];

    const int tid = threadIdx.x;
    const int warpLocal = tid >> 5;
    const int lane = tid & 31;
    const int t = lane >> 3;
    const int q = lane & 7;
    const int q9 = q * 9;
    const int q10 = q * 10;

    const int w = blockIdx.x * WPB + warpLocal;   // global warp unit, 8192 total
    const int b = w >> 10;
    const int rem = w & 1023;
    const int tr = rem >> 4;
    const int sp = rem & 15;
    const int col0 = sp << 5;                      // warp's 32-column span start
    const int row0 = tr << 3;

    float* S = &scr[warpLocal][0];

    // ===== issue image loads FIRST: 6 LDG.128/thread in flight over table init =====
    const int ra = lane >> 3;          // 0..3
    const int qc = lane & 7;           // 0..7 (quad-column)
    const float* gbase = img + (size_t)b * 3 * PLANE + (size_t)(row0) * HW + col0 + (qc << 2);
    float4 v0 = *(const float4*)(gbase + (size_t)ra * HW);
    float4 v1 = *(const float4*)(gbase + (size_t)(ra + 4) * HW);
    float4 v2 = *(const float4*)(gbase + PLANE + (size_t)ra * HW);
    float4 v3 = *(const float4*)(gbase + PLANE + (size_t)(ra + 4) * HW);
    float4 v4 = *(const float4*)(gbase + 2 * PLANE + (size_t)ra * HW);
    float4 v5 = *(const float4*)(gbase + 2 * PLANE + (size_t)(ra + 4) * HW);

    // ===== per-warp redundant table init (benign identical-value races) =====
    // No block barrier anywhere in this kernel: each warp writes ALL 128
    // entries itself, so its own __syncwarp suffices. 4 uniform iterations.
    #pragma unroll
    for (int k = 0; k < 4; k++) {
        int idx128 = lane + (k << 5);          // k<2: luma 0..63, k>=2: chroma
        int idx = idx128 & 63;
        const float* src = (k < 2) ? q_y : q_c;
        float a = src[idx];
        a = fminf(fmaxf(a, 2.0f), 15.0f);
        float r; asm("rcp.approx.f32 %0,%1;" : "=f"(r) : "f"(a));
        int o = (idx >> 3) * 10 + (idx & 7);
        if (k < 2) { tqvy[o] = a; tqiy[o] = r; }
        else       { tqvc2[o] = PK(a, a); tqic2[o] = PK(r, r); }
    }

    // stage image: S[ch*288 + row*36 + qc*4]  (row-stride 36 -> conflict-free col reads)
    {
        int o = ra * 36 + (qc << 2);
        *(float4*)(S + o)              = v0;
        *(float4*)(S + o + 4 * 36)     = v1;
        *(float4*)(S + 288 + o)        = v2;
        *(float4*)(S + 288 + o + 144)  = v3;
        *(float4*)(S + 576 + o)        = v4;
        *(float4*)(S + 576 + o + 144)  = v5;
    }
    __syncwarp();   // covers this warp's table writes AND stage writes

    // column gather: lane owns image column col0+lane
    float R[8], G[8], Bc[8];
    #pragma unroll
    for (int r = 0; r < 8; r++) R[r]  = S[r * 36 + lane];
    #pragma unroll
    for (int r = 0; r < 8; r++) G[r]  = S[288 + r * 36 + lane];
    #pragma unroll
    for (int r = 0; r < 8; r++) Bc[r] = S[576 + r * 36 + lane];

    // packed chroma color constants: lo=cb, hi=cr
    const u64 KRC = PK(-0.168736f,  0.5f);
    const u64 KGC = PK(-0.331264f, -0.418688f);
    const u64 KBC = PK( 0.5f,      -0.081312f);
    const u64 HALF2 = PK(0.5f, 0.5f);

    float Y[8];
    u64   C[8];
    #pragma unroll
    for (int r = 0; r < 8; r++) {
        float Rr = __saturatef(R[r]);
        float Gr = __saturatef(G[r]);
        float Br = __saturatef(Bc[r]);
        Y[r] = 0.299f * Rr + 0.587f * Gr + 0.114f * Br;
        C[r] = ffma2(PK(Rr, Rr), KRC, ffma2(PK(Gr, Gr), KGC, ffma2(PK(Br, Br), KBC, HALF2)));
    }
    __syncwarp();   // WAR: transpose windows reuse the staging buffer

    float* tfq = S + t * 72;                    // Y transpose region [0,288)
    u64*   t2q = (u64*)(S + 288) + t * 72;      // C transpose region [288,864)

    // ===== phase 1: column DCT =====
    mulD(Y);
    mulD2(C);

    // ---- shared transpose window 1 ----
    #pragma unroll
    for (int i = 0; i < 8; i++) tfq[i * 9 + q] = Y[i];
    #pragma unroll
    for (int i = 0; i < 8; i++) t2q[i * 9 + q] = C[i];
    __syncwarp();
    #pragma unroll
    for (int i = 0; i < 8; i++) Y[i] = tfq[q9 + i];
    #pragma unroll
    for (int i = 0; i < 8; i++) C[i] = t2q[q9 + i];
    __syncwarp();   // WAR guard before window 2 reuses buffers

    // ===== phase 2: row DCT + quant + column DCT =====
    mulDT(Y);
    mulDT2(C);
    // luma quant in f32x2 pairs (LDS.64 table fetch), chroma via u64 tables
    #pragma unroll
    for (int lp = 0; lp < 4; lp++) {
        int l = lp * 2;
        u64 qi2 = *(const u64*)&tqiy[q10 + l];
        u64 qv2 = *(const u64*)&tqvy[q10 + l];
        u64 y2 = quant2p(PK(Y[l], Y[l + 1]), qi2, qv2);
        UPK(y2, Y[l], Y[l + 1]);
        C[l]     = quant2p(C[l],     tqic2[q10 + l],     tqvc2[q10 + l]);
        C[l + 1] = quant2p(C[l + 1], tqic2[q10 + l + 1], tqvc2[q10 + l + 1]);
    }
    mulD(Y);
    mulD2(C);

    // ---- shared transpose window 2 ----
    #pragma unroll
    for (int i = 0; i < 8; i++) tfq[i * 9 + q] = Y[i];
    #pragma unroll
    for (int i = 0; i < 8; i++) t2q[i * 9 + q] = C[i];
    __syncwarp();
    #pragma unroll
    for (int i = 0; i < 8; i++) Y[i] = tfq[q9 + i];
    #pragma unroll
    for (int i = 0; i < 8; i++) C[i] = t2q[q9 + i];

    // ===== phase 3: final row DCT + inverse color + store =====
    mulDT(Y);
    mulDT2(C);

    float* obase = out + (size_t)b * 3 * PLANE + (size_t)row0 * HW + col0 + lane;
    #pragma unroll
    for (int r = 0; r < 8; r++) {
        float cb, cr;
        UPK(C[r], cb, cr);
        cb -= 0.5f; cr -= 0.5f;
        float y2 = Y[r];
        float Rr = y2 + 1.402f * cr;
        float Gr = y2 - 0.344136f * cb - 0.714136f * cr;
        float Br = y2 + 1.772f * cb;
        obase[r * HW]             = __saturatef(Rr);
        obase[PLANE + r * HW]     = __saturatef(Gr);
        obase[2 * PLANE + r * HW] = __saturatef(Br);
    }
}

extern "C" void kernel_launch(void* const* d_in, const int* in_sizes, int n_in,
                              void* d_out, int out_size) {
    const float* img = (const float*)d_in[0];
    const float* qy  = (const float*)d_in[1];
    const float* qc  = (const float*)d_in[2];
    float* out = (float*)d_out;

    int nb = in_sizes[0] / (3 * HW * HW);          // batch (8)
    int warps = nb * (HW / 8) * (HW / 32);         // 8192
    int blocks = warps / WPB;                      // 2048
    jpeg_kernel<<<blocks, TPB>>>(img, qy, qc, out);
}